// round 12
// baseline (speedup 1.0000x reference)
#include <cuda_runtime.h>
#include <cuda_fp16.h>
#include <cuda_bf16.h>
#include <cstdint>

// ---------------------------------------------------------------------------
// ALIGNN layer: two GatedGCN blocks.
// GEMMs via mma.sync fp16 (HMMA), single product (A,W rounded to fp16).
// R11: GEMM retiled 64x128 per CTA (warp tile 32x32, 48KB smem, 3 CTAs/SM,
// 24 warps) — GEMM was latency-bound at occ 2 (tensor pipe 23.5%).
// ---------------------------------------------------------------------------

#define N_NODES  100000LL
#define N_EDGES  600000LL
#define N_ANGLES 600000LL
#define D        128

typedef unsigned long long u64;
typedef unsigned int u32;

// ------------------------- scratch (device globals) ------------------------
__device__ unsigned short g_NB1[100000LL * 512];  // half: Ah|Bh|Dh|Eh
__device__ unsigned short g_Ce [600000LL * 128];  // half
__device__ unsigned short g_NB2[600000LL * 512];  // half: Ae|Be|De|Ee
__device__ unsigned short g_Ca [600000LL * 128];  // half
__device__ unsigned short g_e1 [600000LL * 128];  // half (layer-2 GEMM input)
__device__ unsigned short g_num1[100000LL * 128]; // half (f16x2 red targets)
__device__ unsigned short g_den1[100000LL * 128];
__device__ unsigned short g_num2[600000LL * 128];
__device__ unsigned short g_den2[600000LL * 128];
// Pre-rounded, pre-swizzled fp16 weights: 10 matrices x 32KB
__device__ __align__(128) char g_Wsplit[10 * 32768];

// ------------------------------ helpers -------------------------------------
__device__ __forceinline__ u32 smem_u32(const void* p) {
    u32 a;
    asm("{ .reg .u64 t; cvta.to.shared.u64 t, %1; cvt.u32.u64 %0, t; }"
        : "=r"(a) : "l"(p));
    return a;
}

// Tile image: rows x 128 cols fp16, row stride 256B, 16B chunks
// XOR-swizzled by (row & 7) for conflict-free ldmatrix.
__device__ __forceinline__ u32 tile_off(int r, int k) {
    return (u32)r * 256 + ((u32)(((k >> 3) ^ (r & 7))) << 4) + ((u32)(k & 7) << 1);
}

__device__ __forceinline__ void ldsm_x4(u32 addr, u32& r0, u32& r1, u32& r2, u32& r3) {
    asm volatile("ldmatrix.sync.aligned.m8n8.x4.shared.b16 {%0,%1,%2,%3}, [%4];"
                 : "=r"(r0), "=r"(r1), "=r"(r2), "=r"(r3) : "r"(addr));
}

__device__ __forceinline__ void mma_f16(float* c, const u32* a, const u32* b) {
    asm volatile(
        "mma.sync.aligned.m16n8k16.row.col.f32.f16.f16.f32 "
        "{%0,%1,%2,%3}, {%4,%5,%6,%7}, {%8,%9}, {%0,%1,%2,%3};"
        : "+f"(c[0]), "+f"(c[1]), "+f"(c[2]), "+f"(c[3])
        : "r"(a[0]), "r"(a[1]), "r"(a[2]), "r"(a[3]), "r"(b[0]), "r"(b[1]));
}

__device__ __forceinline__ void cpasync16(u32 dst, const void* src) {
    asm volatile("cp.async.cg.shared.global [%0], [%1], 16;"
                 :: "r"(dst), "l"(src));
}

// cp.async with src-size predicate: srcsz==0 -> fill 16B of zeros
__device__ __forceinline__ void cpasync16z(u32 dst, const void* src, int srcsz) {
    asm volatile("cp.async.cg.shared.global [%0], [%1], 16, %2;"
                 :: "r"(dst), "l"(src), "r"(srcsz));
}

__device__ __forceinline__ void red_h2(__half* p, float a, float b) {
    __half2 h = __floats2half2_rn(a, b);
    asm volatile("red.global.add.noftz.f16x2 [%0], %1;"
                 :: "l"(p), "r"(*(u32*)&h) : "memory");
}

// SMEM layout (byte offsets): A tile (16KB, 64 rows) | W (32KB)
#define SA_H 0
#define SW0  16384
#define GEMM_SMEM 49152

// --------------------------- weight prep kernel -----------------------------
__global__ void wprep_kernel(const float* __restrict__ w1,
                             const float* __restrict__ w2,
                             char* __restrict__ dst)
{
    int mat = blockIdx.x;                       // 0..9
    const float* W = (mat < 5) ? (w1 + mat * 16384) : (w2 + (mat - 5) * 16384);
    char* base = dst + (long long)mat * 32768;
    for (int i = threadIdx.x; i < 16384; i += blockDim.x) {
        int n = i >> 7, k = i & 127;
        float v = W[k * 128 + n];
        *(__half*)(base + tile_off(n, k)) = __float2half_rn(v);
    }
}

// ------------------------------ HMMA GEMM -----------------------------------
// For j in [0, nmat): C[:, j*128 : +128] = A[M,128] @ W[nibble_j(wmap)] + bias
// CTA tile 64(M) x 128(N), 256 threads, warp tile 32x32, 3 CTAs/SM.
// A input fp32 (aHalf=0, sync LDG) or fp16 (aHalf=1, async cp). Output fp16.
extern "C" __global__ __launch_bounds__(256, 3) void gemm_mma(
    const void* __restrict__ Ain, int aHalf, const char* __restrict__ Wp,
    const float* __restrict__ b1, const float* __restrict__ b2,
    __half* __restrict__ C, long long M, int ldc, int wmap, int nmat)
{
    extern __shared__ char smem[];
    const u32 sb = smem_u32(smem);
    const int tid = threadIdx.x, lane = tid & 31, wid = tid >> 5;
    const int wm = wid & 1;          // 0..1 -> 32-row slice
    const int wn = wid >> 1;         // 0..3 -> 32-col slice
    const long long row0 = (long long)blockIdx.x * 64;

    // One cp.async group: W0 (+ A when fp16). wait_group 0 at each j-top.
    {
        int mat = wmap & 0xF;
        const char* ws = Wp + (long long)mat * 32768;
        #pragma unroll 4
        for (int i = tid; i < 2048; i += 256)
            cpasync16(sb + SW0 + i * 16, ws + (long long)i * 16);
    }
    if (aHalf) {
        // A rows: 256B = 16 chunks of 16B, 1:1 to swizzled image. Zero past M.
        const char* Ab = (const char*)Ain;
        #pragma unroll 2
        for (int i = tid; i < 1024; i += 256) {
            int r = i >> 4, ch = i & 15;
            long long row = row0 + r;
            u32 dst = sb + SA_H + (u32)r * 256 + ((u32)(ch ^ (r & 7)) << 4);
            cpasync16z(dst, Ab + row * 256 + ch * 16, (row < M) ? 16 : 0);
        }
    }
    asm volatile("cp.async.commit_group;");

    if (!aHalf) {
        // fp32 A: synchronous load + convert + swizzled store (64 rows)
        const float4* A4 = (const float4*)Ain;
        #pragma unroll 4
        for (int i = tid; i < 2048; i += 256) {
            int r = i >> 5, c4 = i & 31;
            long long row = row0 + r;
            float4 v = (row < M) ? A4[row * 32 + c4]
                                 : make_float4(0.f, 0.f, 0.f, 0.f);
            __half2 h01 = __floats2half2_rn(v.x, v.y);
            __half2 h23 = __floats2half2_rn(v.z, v.w);
            *(uint2*)(smem + SA_H + tile_off(r, c4 * 4)) =
                make_uint2(*(u32*)&h01, *(u32*)&h23);
        }
    }

    // ldmatrix lane addressing constants
    const int rA = wm * 32 + (lane & 15);       // + mf*16 per frag
    const int haA = lane >> 4;
    const int rBoff = (lane & 7) + ((lane >> 4) << 3);
    const int hbB = (lane >> 3) & 1;

    u32 aBase[2]; int aSel[2];
    #pragma unroll
    for (int mf = 0; mf < 2; mf++) {
        int r = rA + mf * 16;
        aBase[mf] = sb + SA_H + (u32)r * 256;
        aSel[mf] = r & 7;
    }
    u32 bBase[2]; int bSel[2];
    #pragma unroll
    for (int np = 0; np < 2; np++) {
        int r = wn * 32 + np * 16 + rBoff;
        bBase[np] = sb + SW0 + (u32)r * 256;
        bSel[np] = r & 7;
    }

    const int mloc = wm * 32 + (lane >> 2);

    #pragma unroll 1
    for (int j = 0; j < nmat; j++) {
        const int mat = (wmap >> (4 * j)) & 0xF;
        const float* bias = (mat < 5) ? (b1 + mat * 128) : (b2 + (mat - 5) * 128);

        asm volatile("cp.async.wait_group 0;");
        __syncthreads();   // W_j (+A at j=0) visible to all warps

        float acc[2][4][4];
        #pragma unroll
        for (int mf = 0; mf < 2; mf++)
            #pragma unroll
            for (int nf = 0; nf < 4; nf++)
                #pragma unroll
                for (int q = 0; q < 4; q++) acc[mf][nf][q] = 0.f;

        #pragma unroll 1
        for (int kb = 0; kb < 8; kb++) {
            const int c2 = kb * 2;
            u32 ah[2][4], bh[4][2];
            #pragma unroll
            for (int mf = 0; mf < 2; mf++) {
                u32 x = (u32)((c2 + haA) ^ aSel[mf]) << 4;
                ldsm_x4(aBase[mf] + x, ah[mf][0], ah[mf][1], ah[mf][2], ah[mf][3]);
            }
            #pragma unroll
            for (int np = 0; np < 2; np++) {
                u32 x = (u32)((c2 + hbB) ^ bSel[np]) << 4;
                ldsm_x4(bBase[np] + x, bh[2*np][0], bh[2*np][1],
                                       bh[2*np+1][0], bh[2*np+1][1]);
            }
            #pragma unroll
            for (int mf = 0; mf < 2; mf++)
                #pragma unroll
                for (int nf = 0; nf < 4; nf++)
                    mma_f16(acc[mf][nf], ah[mf], bh[nf]);
        }

        __syncthreads();   // all warps done reading W buffer
        if (j + 1 < nmat) {
            int mat2 = (wmap >> (4 * (j + 1))) & 0xF;
            const char* ws = Wp + (long long)mat2 * 32768;
            #pragma unroll 4
            for (int i = tid; i < 2048; i += 256)
                cpasync16(sb + SW0 + i * 16, ws + (long long)i * 16);
            asm volatile("cp.async.commit_group;");
        }

        // Epilogue (overlaps W_{j+1} load): add bias, round to fp16, store
        __half* Cj = C + j * 128;
        #pragma unroll
        for (int mf = 0; mf < 2; mf++) {
            long long rowa = row0 + mloc + mf * 16;
            long long rowb = rowa + 8;
            #pragma unroll
            for (int nf = 0; nf < 4; nf++) {
                int n = wn * 32 + nf * 8 + (lane & 3) * 2;
                float bx = __ldg(bias + n), by = __ldg(bias + n + 1);
                if (rowa < M) {
                    __half2 o = __floats2half2_rn(acc[mf][nf][0] + bx,
                                                  acc[mf][nf][1] + by);
                    *(__half2*)(Cj + rowa * (long long)ldc + n) = o;
                }
                if (rowb < M) {
                    __half2 o = __floats2half2_rn(acc[mf][nf][2] + bx,
                                                  acc[mf][nf][3] + by);
                    *(__half2*)(Cj + rowb * (long long)ldc + n) = o;
                }
            }
        }
    }
}

// ------------------------------ edge kernel ---------------------------------
// One warp per edge. Inputs fp16, math fp32, num/den fp16x2 reductions.
// eout: fp16 (layer 1 -> e1 scratch) or fp32 (layer 2 -> final a_out).
__device__ __forceinline__ float sigmoidf(float x) {
    return 1.0f / (1.0f + __expf(-x));
}

__device__ __forceinline__ float4 h4_to_f4(uint2 v) {
    float2 a = __half22float2(*(__half2*)&v.x);
    float2 b = __half22float2(*(__half2*)&v.y);
    return make_float4(a.x, a.y, b.x, b.y);
}

template <bool OUT_HALF>
__global__ __launch_bounds__(256) void edge_kernel(
    const __half* __restrict__ Ce, const __half* __restrict__ NB,
    const int* __restrict__ src, const int* __restrict__ dst,
    __half* __restrict__ num, __half* __restrict__ den,
    void* __restrict__ eout, long long E)
{
    long long e = (long long)blockIdx.x * 8 + (threadIdx.x >> 5);
    if (e >= E) return;
    const int lane = threadIdx.x & 31;
    const int s = __ldg(src + e);
    const int d = __ldg(dst + e);

    const long long eo = e * 128 + lane * 4;
    const float4 ce = h4_to_f4(*(const uint2*)(Ce + eo));
    const __half* nbs = NB + (long long)s * 512;
    const __half* nbd = NB + (long long)d * 512;
    const float4 dh = h4_to_f4(*(const uint2*)(nbs + 256 + lane * 4)); // D-gate
    const float4 eh = h4_to_f4(*(const uint2*)(nbd + 384 + lane * 4)); // E-gate
    const float4 bh = h4_to_f4(*(const uint2*)(nbs + 128 + lane * 4)); // B msg

    float4 en;
    en.x = ce.x + dh.x + eh.x;
    en.y = ce.y + dh.y + eh.y;
    en.z = ce.z + dh.z + eh.z;
    en.w = ce.w + dh.w + eh.w;

    float4 sg;
    sg.x = sigmoidf(en.x); sg.y = sigmoidf(en.y);
    sg.z = sigmoidf(en.z); sg.w = sigmoidf(en.w);

    __half* np = num + (long long)d * 128 + lane * 4;
    __half* dp = den + (long long)d * 128 + lane * 4;
    red_h2(np,     sg.x * bh.x, sg.y * bh.y);
    red_h2(np + 2, sg.z * bh.z, sg.w * bh.w);
    red_h2(dp,     sg.x, sg.y);
    red_h2(dp + 2, sg.z, sg.w);

    if (OUT_HALF) {
        __half2 r01 = __floats2half2_rn(fmaxf(en.x, 0.f), fmaxf(en.y, 0.f));
        __half2 r23 = __floats2half2_rn(fmaxf(en.z, 0.f), fmaxf(en.w, 0.f));
        *(uint2*)((__half*)eout + eo) = make_uint2(*(u32*)&r01, *(u32*)&r23);
    } else {
        float4 ro;
        ro.x = fmaxf(en.x, 0.f); ro.y = fmaxf(en.y, 0.f);
        ro.z = fmaxf(en.z, 0.f); ro.w = fmaxf(en.w, 0.f);
        *(float4*)((float*)eout + eo) = ro;
    }
}

// ------------------------------ finalize ------------------------------------
// out[i] = relu(Ah[i] + num[i] / (den[i] + eps)); Ah, num, den fp16.
__global__ __launch_bounds__(256) void finalize_kernel(
    const __half* __restrict__ Abuf, long long lda,
    const __half* __restrict__ num, const __half* __restrict__ den,
    float* __restrict__ outp, long long N)
{
    long long i = (long long)blockIdx.x * 256 + threadIdx.x;   // group-of-4 idx
    if (i >= N * 32) return;
    long long row = i >> 5;
    int c = (int)(i & 31);
    float4 a = h4_to_f4(*(const uint2*)(Abuf + row * lda + c * 4));
    float4 n = h4_to_f4(*(const uint2*)(num + i * 4));
    float4 dd = h4_to_f4(*(const uint2*)(den + i * 4));
    float4 o;
    o.x = fmaxf(a.x + n.x / (dd.x + 1e-6f), 0.f);
    o.y = fmaxf(a.y + n.y / (dd.y + 1e-6f), 0.f);
    o.z = fmaxf(a.z + n.z / (dd.z + 1e-6f), 0.f);
    o.w = fmaxf(a.w + n.w / (dd.w + 1e-6f), 0.f);
    ((float4*)outp)[i] = o;
}

// ------------------------------ launch --------------------------------------
extern "C" void kernel_launch(void* const* d_in, const int* in_sizes, int n_in,
                              void* d_out, int out_size)
{
    const float* node  = (const float*)d_in[0];
    const float* edge  = (const float*)d_in[1];
    const float* angle = (const float*)d_in[2];
    const int*   gei   = (const int*)d_in[3];
    const int*   lei   = (const int*)d_in[4];
    const float* w1    = (const float*)d_in[5];
    const float* b1    = (const float*)d_in[6];
    const float* w2    = (const float*)d_in[7];
    const float* b2    = (const float*)d_in[8];

    float* out   = (float*)d_out;
    float* h_out = out;
    float* e_out = out + N_NODES * D;
    float* a_out = out + N_NODES * D + N_EDGES * D;

    __half *NB1, *Ce, *NB2, *Ca, *e1, *num1, *den1, *num2, *den2;
    char* Wsp;
    cudaGetSymbolAddress((void**)&NB1,  g_NB1);
    cudaGetSymbolAddress((void**)&Ce,   g_Ce);
    cudaGetSymbolAddress((void**)&NB2,  g_NB2);
    cudaGetSymbolAddress((void**)&Ca,   g_Ca);
    cudaGetSymbolAddress((void**)&e1,   g_e1);
    cudaGetSymbolAddress((void**)&num1, g_num1);
    cudaGetSymbolAddress((void**)&den1, g_den1);
    cudaGetSymbolAddress((void**)&num2, g_num2);
    cudaGetSymbolAddress((void**)&den2, g_den2);
    cudaGetSymbolAddress((void**)&Wsp,  g_Wsplit);

    cudaFuncSetAttribute(gemm_mma,
                         cudaFuncAttributeMaxDynamicSharedMemorySize, GEMM_SMEM);

    // Side stream + events for fork/join inside graph capture.
    cudaStream_t s1;
    cudaStreamCreateWithFlags(&s1, cudaStreamNonBlocking);
    cudaEvent_t ev_fork, ev_ms, ev_g2, ev_g4, ev_e1, ev_f1;
    cudaEventCreateWithFlags(&ev_fork, cudaEventDisableTiming);
    cudaEventCreateWithFlags(&ev_ms,   cudaEventDisableTiming);
    cudaEventCreateWithFlags(&ev_g2,   cudaEventDisableTiming);
    cudaEventCreateWithFlags(&ev_g4,   cudaEventDisableTiming);
    cudaEventCreateWithFlags(&ev_e1,   cudaEventDisableTiming);
    cudaEventCreateWithFlags(&ev_f1,   cudaEventDisableTiming);

    // Fork s1 from the capture-origin (default) stream.
    cudaEventRecord(ev_fork, 0);
    cudaStreamWaitEvent(s1, ev_fork, 0);

    // s1: zero segment-sum accumulators (overlaps wprep/G1 on s0)
    cudaMemsetAsync(num1, 0, N_NODES * D * sizeof(__half), s1);
    cudaMemsetAsync(den1, 0, N_NODES * D * sizeof(__half), s1);
    cudaMemsetAsync(num2, 0, N_EDGES * D * sizeof(__half), s1);
    cudaMemsetAsync(den2, 0, N_EDGES * D * sizeof(__half), s1);
    cudaEventRecord(ev_ms, s1);

    // s0: weight prep, then layer-1 GEMMs (row tile 64 -> grids doubled)
    wprep_kernel<<<10, 256>>>(w1, w2, Wsp);
    gemm_mma<<<1563, 256, GEMM_SMEM>>>(node, 0, Wsp, b1, b2, NB1,
                                       N_NODES, 512, 0x4310, 4);
    gemm_mma<<<9375, 256, GEMM_SMEM>>>(edge, 0, Wsp, b1, b2, Ce,
                                       N_EDGES, 128, 0x2, 1);
    cudaEventRecord(ev_g2, 0);

    // s1: angle GEMM (needs wprep; scheduled after G2 so it overlaps E1)
    cudaStreamWaitEvent(s1, ev_g2, 0);
    gemm_mma<<<9375, 256, GEMM_SMEM, s1>>>(angle, 0, Wsp, b1, b2, Ca,
                                           N_ANGLES, 128, 0x7, 1);
    cudaEventRecord(ev_g4, s1);

    // s0: edge1 (needs G1, G2, memsets) — overlaps with Ca GEMM on s1
    cudaStreamWaitEvent(0, ev_ms, 0);
    edge_kernel<true><<<75000, 256>>>(Ce, NB1, gei, gei + N_EDGES,
                                      num1, den1, e1, N_EDGES);
    cudaEventRecord(ev_e1, 0);

    // s1: finalize1 (needs edge1) — overlaps with e1->NB2 GEMM on s0
    cudaStreamWaitEvent(s1, ev_e1, 0);
    finalize_kernel<<<12500, 256, 0, s1>>>(NB1, 512, num1, den1,
                                           h_out, N_NODES);
    cudaEventRecord(ev_f1, s1);

    // s0: layer-2 big GEMM (needs e1), then edge2 (needs Ca too), finalize2
    gemm_mma<<<9375, 256, GEMM_SMEM>>>(e1, 1, Wsp, b1, b2, NB2,
                                       N_EDGES, 512, 0x9865, 4);
    cudaStreamWaitEvent(0, ev_g4, 0);
    edge_kernel<false><<<75000, 256>>>(Ca, NB2, lei, lei + N_ANGLES,
                                       num2, den2, a_out, N_ANGLES);
    finalize_kernel<<<75000, 256>>>(NB2, 512, num2, den2, e_out, N_EDGES);

    // Join s1 back into s0 before returning (h_out must be ordered).
    cudaStreamWaitEvent(0, ev_f1, 0);

    cudaEventDestroy(ev_fork);
    cudaEventDestroy(ev_ms);
    cudaEventDestroy(ev_g2);
    cudaEventDestroy(ev_g4);
    cudaEventDestroy(ev_e1);
    cudaEventDestroy(ev_f1);
    cudaStreamDestroy(s1);
}

// round 13
// speedup vs baseline: 1.0642x; 1.0642x over previous
#include <cuda_runtime.h>
#include <cuda_fp16.h>
#include <cuda_bf16.h>
#include <cstdint>

// ---------------------------------------------------------------------------
// ALIGNN layer: two GatedGCN blocks.
// GEMMs via mma.sync fp16 (HMMA), single product (A,W rounded to fp16).
// R13: Ce/Ca GEMMs fused with the edge kernels — GEMM tile staged in smem,
// same CTA gathers gates, applies sigmoid, does fp16x2 reductions, writes
// e1/a_out. Removes ~600MB of DRAM round-trip and two launches.
// ---------------------------------------------------------------------------

#define N_NODES  100000LL
#define N_EDGES  600000LL
#define N_ANGLES 600000LL
#define D        128

typedef unsigned long long u64;
typedef unsigned int u32;

// ------------------------- scratch (device globals) ------------------------
__device__ unsigned short g_NB1[100000LL * 512];  // half: Ah|Bh|Dh|Eh
__device__ unsigned short g_NB2[600000LL * 512];  // half: Ae|Be|De|Ee
__device__ unsigned short g_e1 [600000LL * 128];  // half (layer-2 GEMM input)
__device__ unsigned short g_num1[100000LL * 128]; // half (f16x2 red targets)
__device__ unsigned short g_den1[100000LL * 128];
__device__ unsigned short g_num2[600000LL * 128];
__device__ unsigned short g_den2[600000LL * 128];
// Pre-rounded, pre-swizzled fp16 weights: 10 matrices x 32KB
__device__ __align__(128) char g_Wsplit[10 * 32768];

// ------------------------------ helpers -------------------------------------
__device__ __forceinline__ u32 smem_u32(const void* p) {
    u32 a;
    asm("{ .reg .u64 t; cvta.to.shared.u64 t, %1; cvt.u32.u64 %0, t; }"
        : "=r"(a) : "l"(p));
    return a;
}

// Tile image: rows x 128 cols fp16, row stride 256B, 16B chunks
// XOR-swizzled by (row & 7) for conflict-free ldmatrix.
__device__ __forceinline__ u32 tile_off(int r, int k) {
    return (u32)r * 256 + ((u32)(((k >> 3) ^ (r & 7))) << 4) + ((u32)(k & 7) << 1);
}

__device__ __forceinline__ void ldsm_x4(u32 addr, u32& r0, u32& r1, u32& r2, u32& r3) {
    asm volatile("ldmatrix.sync.aligned.m8n8.x4.shared.b16 {%0,%1,%2,%3}, [%4];"
                 : "=r"(r0), "=r"(r1), "=r"(r2), "=r"(r3) : "r"(addr));
}

__device__ __forceinline__ void mma_f16(float* c, const u32* a, const u32* b) {
    asm volatile(
        "mma.sync.aligned.m16n8k16.row.col.f32.f16.f16.f32 "
        "{%0,%1,%2,%3}, {%4,%5,%6,%7}, {%8,%9}, {%0,%1,%2,%3};"
        : "+f"(c[0]), "+f"(c[1]), "+f"(c[2]), "+f"(c[3])
        : "r"(a[0]), "r"(a[1]), "r"(a[2]), "r"(a[3]), "r"(b[0]), "r"(b[1]));
}

__device__ __forceinline__ void cpasync16(u32 dst, const void* src) {
    asm volatile("cp.async.cg.shared.global [%0], [%1], 16;"
                 :: "r"(dst), "l"(src));
}

__device__ __forceinline__ void cpasync16z(u32 dst, const void* src, int srcsz) {
    asm volatile("cp.async.cg.shared.global [%0], [%1], 16, %2;"
                 :: "r"(dst), "l"(src), "r"(srcsz));
}

__device__ __forceinline__ void red_h2(__half* p, float a, float b) {
    __half2 h = __floats2half2_rn(a, b);
    asm volatile("red.global.add.noftz.f16x2 [%0], %1;"
                 :: "l"(p), "r"(*(u32*)&h) : "memory");
}

__device__ __forceinline__ float sigmoidf(float x) {
    return 1.0f / (1.0f + __expf(-x));
}

__device__ __forceinline__ float4 h4_to_f4(uint2 v) {
    float2 a = __half22float2(*(__half2*)&v.x);
    float2 b = __half22float2(*(__half2*)&v.y);
    return make_float4(a.x, a.y, b.x, b.y);
}

// gemm_mma smem: A tile (16KB, swizzled, 64 rows) | W (32KB)
#define SA_H 0
#define SW0  16384
#define GEMM_SMEM 49152
// fused kernel smem: EP/A region (17408B: A swizzled 16KB OR 64x272B tile)
// | W (32KB) at 17408 (128B aligned)
#define EPS   272
#define FW0   17408
#define FUSED_SMEM (17408 + 32768)

// --------------------------- weight prep kernel -----------------------------
__global__ void wprep_kernel(const float* __restrict__ w1,
                             const float* __restrict__ w2,
                             char* __restrict__ dst)
{
    int mat = blockIdx.x;                       // 0..9
    const float* W = (mat < 5) ? (w1 + mat * 16384) : (w2 + (mat - 5) * 16384);
    char* base = dst + (long long)mat * 32768;
    for (int i = threadIdx.x; i < 16384; i += blockDim.x) {
        int n = i >> 7, k = i & 127;
        float v = W[k * 128 + n];
        *(__half*)(base + tile_off(n, k)) = __float2half_rn(v);
    }
}

// ------------------------------ HMMA GEMM (4-mat) ---------------------------
// For j in [0, nmat): C[:, j*128 : +128] = A[M,128] @ W[nibble_j(wmap)] + bias
// CTA tile 64(M) x 128(N), 256 threads, warp tile 32x32, 3 CTAs/SM.
extern "C" __global__ __launch_bounds__(256, 3) void gemm_mma(
    const void* __restrict__ Ain, int aHalf, const char* __restrict__ Wp,
    const float* __restrict__ b1, const float* __restrict__ b2,
    __half* __restrict__ C, long long M, int ldc, int wmap, int nmat)
{
    extern __shared__ char smem[];
    const u32 sb = smem_u32(smem);
    const int tid = threadIdx.x, lane = tid & 31, wid = tid >> 5;
    const int wm = wid & 1;
    const int wn = wid >> 1;
    const long long row0 = (long long)blockIdx.x * 64;

    {
        int mat = wmap & 0xF;
        const char* ws = Wp + (long long)mat * 32768;
        #pragma unroll 4
        for (int i = tid; i < 2048; i += 256)
            cpasync16(sb + SW0 + i * 16, ws + (long long)i * 16);
    }
    if (aHalf) {
        const char* Ab = (const char*)Ain;
        #pragma unroll 2
        for (int i = tid; i < 1024; i += 256) {
            int r = i >> 4, ch = i & 15;
            long long row = row0 + r;
            u32 dst = sb + SA_H + (u32)r * 256 + ((u32)(ch ^ (r & 7)) << 4);
            cpasync16z(dst, Ab + row * 256 + ch * 16, (row < M) ? 16 : 0);
        }
    }
    asm volatile("cp.async.commit_group;");

    if (!aHalf) {
        const float4* A4 = (const float4*)Ain;
        #pragma unroll 4
        for (int i = tid; i < 2048; i += 256) {
            int r = i >> 5, c4 = i & 31;
            long long row = row0 + r;
            float4 v = (row < M) ? A4[row * 32 + c4]
                                 : make_float4(0.f, 0.f, 0.f, 0.f);
            __half2 h01 = __floats2half2_rn(v.x, v.y);
            __half2 h23 = __floats2half2_rn(v.z, v.w);
            *(uint2*)(smem + SA_H + tile_off(r, c4 * 4)) =
                make_uint2(*(u32*)&h01, *(u32*)&h23);
        }
    }

    const int rA = wm * 32 + (lane & 15);
    const int haA = lane >> 4;
    const int rBoff = (lane & 7) + ((lane >> 4) << 3);
    const int hbB = (lane >> 3) & 1;

    u32 aBase[2]; int aSel[2];
    #pragma unroll
    for (int mf = 0; mf < 2; mf++) {
        int r = rA + mf * 16;
        aBase[mf] = sb + SA_H + (u32)r * 256;
        aSel[mf] = r & 7;
    }
    u32 bBase[2]; int bSel[2];
    #pragma unroll
    for (int np = 0; np < 2; np++) {
        int r = wn * 32 + np * 16 + rBoff;
        bBase[np] = sb + SW0 + (u32)r * 256;
        bSel[np] = r & 7;
    }

    const int mloc = wm * 32 + (lane >> 2);

    #pragma unroll 1
    for (int j = 0; j < nmat; j++) {
        const int mat = (wmap >> (4 * j)) & 0xF;
        const float* bias = (mat < 5) ? (b1 + mat * 128) : (b2 + (mat - 5) * 128);

        asm volatile("cp.async.wait_group 0;");
        __syncthreads();

        float acc[2][4][4];
        #pragma unroll
        for (int mf = 0; mf < 2; mf++)
            #pragma unroll
            for (int nf = 0; nf < 4; nf++)
                #pragma unroll
                for (int q = 0; q < 4; q++) acc[mf][nf][q] = 0.f;

        #pragma unroll 1
        for (int kb = 0; kb < 8; kb++) {
            const int c2 = kb * 2;
            u32 ah[2][4], bh[4][2];
            #pragma unroll
            for (int mf = 0; mf < 2; mf++) {
                u32 x = (u32)((c2 + haA) ^ aSel[mf]) << 4;
                ldsm_x4(aBase[mf] + x, ah[mf][0], ah[mf][1], ah[mf][2], ah[mf][3]);
            }
            #pragma unroll
            for (int np = 0; np < 2; np++) {
                u32 x = (u32)((c2 + hbB) ^ bSel[np]) << 4;
                ldsm_x4(bBase[np] + x, bh[2*np][0], bh[2*np][1],
                                       bh[2*np+1][0], bh[2*np+1][1]);
            }
            #pragma unroll
            for (int mf = 0; mf < 2; mf++)
                #pragma unroll
                for (int nf = 0; nf < 4; nf++)
                    mma_f16(acc[mf][nf], ah[mf], bh[nf]);
        }

        __syncthreads();
        if (j + 1 < nmat) {
            int mat2 = (wmap >> (4 * (j + 1))) & 0xF;
            const char* ws = Wp + (long long)mat2 * 32768;
            #pragma unroll 4
            for (int i = tid; i < 2048; i += 256)
                cpasync16(sb + SW0 + i * 16, ws + (long long)i * 16);
            asm volatile("cp.async.commit_group;");
        }

        __half* Cj = C + j * 128;
        #pragma unroll
        for (int mf = 0; mf < 2; mf++) {
            long long rowa = row0 + mloc + mf * 16;
            long long rowb = rowa + 8;
            #pragma unroll
            for (int nf = 0; nf < 4; nf++) {
                int n = wn * 32 + nf * 8 + (lane & 3) * 2;
                float bx = __ldg(bias + n), by = __ldg(bias + n + 1);
                if (rowa < M) {
                    __half2 o = __floats2half2_rn(acc[mf][nf][0] + bx,
                                                  acc[mf][nf][1] + by);
                    *(__half2*)(Cj + rowa * (long long)ldc + n) = o;
                }
                if (rowb < M) {
                    __half2 o = __floats2half2_rn(acc[mf][nf][2] + bx,
                                                  acc[mf][nf][3] + by);
                    *(__half2*)(Cj + rowb * (long long)ldc + n) = o;
                }
            }
        }
    }
}

// --------------------- fused Ce-GEMM + edge kernel --------------------------
// Phase 1: tile Ce[64,128] = A[64,128] @ W + bias  (A fp32; W pre-swizzled)
// Phase 2: tile staged in smem; per-edge: e_new = Ce + Dh[src] + Eh[dst];
//          sigma = sigmoid; num/den fp16x2 reductions; eout = relu(e_new).
template <bool OUT_HALF>
__global__ __launch_bounds__(256, 3) void gemm_edge(
    const float* __restrict__ Ain, const char* __restrict__ Wmat,
    const float* __restrict__ bias, const __half* __restrict__ NB,
    const int* __restrict__ src, const int* __restrict__ dst,
    __half* __restrict__ num, __half* __restrict__ den,
    void* __restrict__ eout, long long E)
{
    extern __shared__ char smem[];
    const u32 sb = smem_u32(smem);
    const int tid = threadIdx.x, lane = tid & 31, wid = tid >> 5;
    const int wm = wid & 1;
    const int wn = wid >> 1;
    const long long row0 = (long long)blockIdx.x * 64;

    // W via cp.async
    #pragma unroll 4
    for (int i = tid; i < 2048; i += 256)
        cpasync16(sb + FW0 + i * 16, Wmat + (long long)i * 16);
    asm volatile("cp.async.commit_group;");

    // A fp32 -> fp16, swizzled into EP region (stride 256 during GEMM)
    {
        const float4* A4 = (const float4*)Ain;
        #pragma unroll 4
        for (int i = tid; i < 2048; i += 256) {
            int r = i >> 5, c4 = i & 31;
            long long row = row0 + r;
            float4 v = (row < E) ? A4[row * 32 + c4]
                                 : make_float4(0.f, 0.f, 0.f, 0.f);
            __half2 h01 = __floats2half2_rn(v.x, v.y);
            __half2 h23 = __floats2half2_rn(v.z, v.w);
            *(uint2*)(smem + tile_off(r, c4 * 4)) =
                make_uint2(*(u32*)&h01, *(u32*)&h23);
        }
    }

    const int rA = wm * 32 + (lane & 15);
    const int haA = lane >> 4;
    const int rBoff = (lane & 7) + ((lane >> 4) << 3);
    const int hbB = (lane >> 3) & 1;

    u32 aBase[2]; int aSel[2];
    #pragma unroll
    for (int mf = 0; mf < 2; mf++) {
        int r = rA + mf * 16;
        aBase[mf] = sb + (u32)r * 256;
        aSel[mf] = r & 7;
    }
    u32 bBase[2]; int bSel[2];
    #pragma unroll
    for (int np = 0; np < 2; np++) {
        int r = wn * 32 + np * 16 + rBoff;
        bBase[np] = sb + FW0 + (u32)r * 256;
        bSel[np] = r & 7;
    }

    asm volatile("cp.async.wait_group 0;");
    __syncthreads();

    float acc[2][4][4];
    #pragma unroll
    for (int mf = 0; mf < 2; mf++)
        #pragma unroll
        for (int nf = 0; nf < 4; nf++)
            #pragma unroll
            for (int q = 0; q < 4; q++) acc[mf][nf][q] = 0.f;

    #pragma unroll 1
    for (int kb = 0; kb < 8; kb++) {
        const int c2 = kb * 2;
        u32 ah[2][4], bh[4][2];
        #pragma unroll
        for (int mf = 0; mf < 2; mf++) {
            u32 x = (u32)((c2 + haA) ^ aSel[mf]) << 4;
            ldsm_x4(aBase[mf] + x, ah[mf][0], ah[mf][1], ah[mf][2], ah[mf][3]);
        }
        #pragma unroll
        for (int np = 0; np < 2; np++) {
            u32 x = (u32)((c2 + hbB) ^ bSel[np]) << 4;
            ldsm_x4(bBase[np] + x, bh[2*np][0], bh[2*np][1],
                                   bh[2*np+1][0], bh[2*np+1][1]);
        }
        #pragma unroll
        for (int mf = 0; mf < 2; mf++)
            #pragma unroll
            for (int nf = 0; nf < 4; nf++)
                mma_f16(acc[mf][nf], ah[mf], bh[nf]);
    }

    __syncthreads();   // all warps done reading A region

    // Stage Ce tile in smem: 64 rows x 128 halfs, row stride EPS=272B
    // (conflict-free STS: word bank = 4*row + (lane&3) + const -> 32 distinct)
    const int mloc = wm * 32 + (lane >> 2);
    #pragma unroll
    for (int mf = 0; mf < 2; mf++) {
        int ra = mloc + mf * 16;
        #pragma unroll
        for (int nf = 0; nf < 4; nf++) {
            int n = wn * 32 + nf * 8 + (lane & 3) * 2;
            float bx = __ldg(bias + n), by = __ldg(bias + n + 1);
            __half2 oa = __floats2half2_rn(acc[mf][nf][0] + bx,
                                           acc[mf][nf][1] + by);
            __half2 ob = __floats2half2_rn(acc[mf][nf][2] + bx,
                                           acc[mf][nf][3] + by);
            *(__half2*)(smem + ra * EPS + n * 2) = oa;
            *(__half2*)(smem + (ra + 8) * EPS + n * 2) = ob;
        }
    }
    __syncthreads();

    // Phase 2: 8 warps x 8 edges each; lane owns cols lane*4..+3
    #pragma unroll 1
    for (int it = 0; it < 8; it++) {
        const int lrow = wid * 8 + it;
        const long long e = row0 + lrow;
        if (e >= E) break;
        const int s = __ldg(src + e);
        const int d = __ldg(dst + e);

        const float4 ce = h4_to_f4(*(const uint2*)(smem + lrow * EPS + lane * 8));
        const __half* nbs = NB + (long long)s * 512;
        const __half* nbd = NB + (long long)d * 512;
        const float4 dh = h4_to_f4(*(const uint2*)(nbs + 256 + lane * 4));
        const float4 eh = h4_to_f4(*(const uint2*)(nbd + 384 + lane * 4));
        const float4 bh = h4_to_f4(*(const uint2*)(nbs + 128 + lane * 4));

        float4 en;
        en.x = ce.x + dh.x + eh.x;
        en.y = ce.y + dh.y + eh.y;
        en.z = ce.z + dh.z + eh.z;
        en.w = ce.w + dh.w + eh.w;

        float4 sg;
        sg.x = sigmoidf(en.x); sg.y = sigmoidf(en.y);
        sg.z = sigmoidf(en.z); sg.w = sigmoidf(en.w);

        __half* np = num + (long long)d * 128 + lane * 4;
        __half* dp = den + (long long)d * 128 + lane * 4;
        red_h2(np,     sg.x * bh.x, sg.y * bh.y);
        red_h2(np + 2, sg.z * bh.z, sg.w * bh.w);
        red_h2(dp,     sg.x, sg.y);
        red_h2(dp + 2, sg.z, sg.w);

        const long long eo = e * 128 + lane * 4;
        if (OUT_HALF) {
            __half2 r01 = __floats2half2_rn(fmaxf(en.x, 0.f), fmaxf(en.y, 0.f));
            __half2 r23 = __floats2half2_rn(fmaxf(en.z, 0.f), fmaxf(en.w, 0.f));
            *(uint2*)((__half*)eout + eo) = make_uint2(*(u32*)&r01, *(u32*)&r23);
        } else {
            float4 ro;
            ro.x = fmaxf(en.x, 0.f); ro.y = fmaxf(en.y, 0.f);
            ro.z = fmaxf(en.z, 0.f); ro.w = fmaxf(en.w, 0.f);
            *(float4*)((float*)eout + eo) = ro;
        }
    }
}

// ------------------------------ finalize ------------------------------------
__global__ __launch_bounds__(256) void finalize_kernel(
    const __half* __restrict__ Abuf, long long lda,
    const __half* __restrict__ num, const __half* __restrict__ den,
    float* __restrict__ outp, long long N)
{
    long long i = (long long)blockIdx.x * 256 + threadIdx.x;   // group-of-4 idx
    if (i >= N * 32) return;
    long long row = i >> 5;
    int c = (int)(i & 31);
    float4 a = h4_to_f4(*(const uint2*)(Abuf + row * lda + c * 4));
    float4 n = h4_to_f4(*(const uint2*)(num + i * 4));
    float4 dd = h4_to_f4(*(const uint2*)(den + i * 4));
    float4 o;
    o.x = fmaxf(a.x + n.x / (dd.x + 1e-6f), 0.f);
    o.y = fmaxf(a.y + n.y / (dd.y + 1e-6f), 0.f);
    o.z = fmaxf(a.z + n.z / (dd.z + 1e-6f), 0.f);
    o.w = fmaxf(a.w + n.w / (dd.w + 1e-6f), 0.f);
    ((float4*)outp)[i] = o;
}

// ------------------------------ launch --------------------------------------
extern "C" void kernel_launch(void* const* d_in, const int* in_sizes, int n_in,
                              void* d_out, int out_size)
{
    const float* node  = (const float*)d_in[0];
    const float* edge  = (const float*)d_in[1];
    const float* angle = (const float*)d_in[2];
    const int*   gei   = (const int*)d_in[3];
    const int*   lei   = (const int*)d_in[4];
    const float* w1    = (const float*)d_in[5];
    const float* b1    = (const float*)d_in[6];
    const float* w2    = (const float*)d_in[7];
    const float* b2    = (const float*)d_in[8];

    float* out   = (float*)d_out;
    float* h_out = out;
    float* e_out = out + N_NODES * D;
    float* a_out = out + N_NODES * D + N_EDGES * D;

    __half *NB1, *NB2, *e1, *num1, *den1, *num2, *den2;
    char* Wsp;
    cudaGetSymbolAddress((void**)&NB1,  g_NB1);
    cudaGetSymbolAddress((void**)&NB2,  g_NB2);
    cudaGetSymbolAddress((void**)&e1,   g_e1);
    cudaGetSymbolAddress((void**)&num1, g_num1);
    cudaGetSymbolAddress((void**)&den1, g_den1);
    cudaGetSymbolAddress((void**)&num2, g_num2);
    cudaGetSymbolAddress((void**)&den2, g_den2);
    cudaGetSymbolAddress((void**)&Wsp,  g_Wsplit);

    cudaFuncSetAttribute(gemm_mma,
                         cudaFuncAttributeMaxDynamicSharedMemorySize, GEMM_SMEM);
    cudaFuncSetAttribute(gemm_edge<true>,
                         cudaFuncAttributeMaxDynamicSharedMemorySize, FUSED_SMEM);
    cudaFuncSetAttribute(gemm_edge<false>,
                         cudaFuncAttributeMaxDynamicSharedMemorySize, FUSED_SMEM);

    // Side stream + events for fork/join inside graph capture.
    cudaStream_t s1;
    cudaStreamCreateWithFlags(&s1, cudaStreamNonBlocking);
    cudaEvent_t ev_fork, ev_ms, ev_e1, ev_f1;
    cudaEventCreateWithFlags(&ev_fork, cudaEventDisableTiming);
    cudaEventCreateWithFlags(&ev_ms,   cudaEventDisableTiming);
    cudaEventCreateWithFlags(&ev_e1,   cudaEventDisableTiming);
    cudaEventCreateWithFlags(&ev_f1,   cudaEventDisableTiming);

    cudaEventRecord(ev_fork, 0);
    cudaStreamWaitEvent(s1, ev_fork, 0);

    // s1: zero segment-sum accumulators (overlaps wprep/G1 on s0)
    cudaMemsetAsync(num1, 0, N_NODES * D * sizeof(__half), s1);
    cudaMemsetAsync(den1, 0, N_NODES * D * sizeof(__half), s1);
    cudaMemsetAsync(num2, 0, N_EDGES * D * sizeof(__half), s1);
    cudaMemsetAsync(den2, 0, N_EDGES * D * sizeof(__half), s1);
    cudaEventRecord(ev_ms, s1);

    // s0: weight prep, node GEMM (4 mats)
    wprep_kernel<<<10, 256>>>(w1, w2, Wsp);
    gemm_mma<<<1563, 256, GEMM_SMEM>>>(node, 0, Wsp, b1, b2, NB1,
                                       N_NODES, 512, 0x4310, 4);

    // s0: fused Ce-GEMM + edge1 (needs NB1 + memsets); writes e1/num1/den1
    cudaStreamWaitEvent(0, ev_ms, 0);
    gemm_edge<true><<<9375, 256, FUSED_SMEM>>>(
        edge, Wsp + 2LL * 32768, b1 + 2 * 128, NB1,
        gei, gei + N_EDGES, num1, den1, e1, N_EDGES);
    cudaEventRecord(ev_e1, 0);

    // s1: finalize1 (needs fused1) — overlaps e1->NB2 GEMM on s0
    cudaStreamWaitEvent(s1, ev_e1, 0);
    finalize_kernel<<<12500, 256, 0, s1>>>(NB1, 512, num1, den1,
                                           h_out, N_NODES);
    cudaEventRecord(ev_f1, s1);

    // s0: layer-2 big GEMM, fused Ca-GEMM + edge2, finalize2
    gemm_mma<<<9375, 256, GEMM_SMEM>>>(e1, 1, Wsp, b1, b2, NB2,
                                       N_EDGES, 512, 0x9865, 4);
    gemm_edge<false><<<9375, 256, FUSED_SMEM>>>(
        angle, Wsp + 7LL * 32768, b2 + 2 * 128, NB2,
        lei, lei + N_ANGLES, num2, den2, a_out, N_ANGLES);
    finalize_kernel<<<75000, 256>>>(NB2, 512, num2, den2, e_out, N_EDGES);

    // Join s1 back into s0 before returning.
    cudaStreamWaitEvent(0, ev_f1, 0);

    cudaEventDestroy(ev_fork);
    cudaEventDestroy(ev_ms);
    cudaEventDestroy(ev_e1);
    cudaEventDestroy(ev_f1);
    cudaStreamDestroy(s1);
}

// round 14
// speedup vs baseline: 1.0669x; 1.0025x over previous
#include <cuda_runtime.h>
#include <cuda_fp16.h>
#include <cuda_bf16.h>
#include <cstdint>

// ---------------------------------------------------------------------------
// ALIGNN layer: two GatedGCN blocks.
// GEMMs via mma.sync fp16 (HMMA), single product (A,W rounded to fp16).
// R13: Ce/Ca GEMMs fused with the edge kernels — GEMM tile staged in smem,
// same CTA gathers gates, applies sigmoid, does fp16x2 reductions, writes
// e1/a_out. Removes ~600MB of DRAM round-trip and two launches.
// ---------------------------------------------------------------------------

#define N_NODES  100000LL
#define N_EDGES  600000LL
#define N_ANGLES 600000LL
#define D        128

typedef unsigned long long u64;
typedef unsigned int u32;

// ------------------------- scratch (device globals) ------------------------
__device__ unsigned short g_NB1[100000LL * 512];  // half: Ah|Bh|Dh|Eh
__device__ unsigned short g_NB2[600000LL * 512];  // half: Ae|Be|De|Ee
__device__ unsigned short g_e1 [600000LL * 128];  // half (layer-2 GEMM input)
__device__ unsigned short g_num1[100000LL * 128]; // half (f16x2 red targets)
__device__ unsigned short g_den1[100000LL * 128];
__device__ unsigned short g_num2[600000LL * 128];
__device__ unsigned short g_den2[600000LL * 128];
// Pre-rounded, pre-swizzled fp16 weights: 10 matrices x 32KB
__device__ __align__(128) char g_Wsplit[10 * 32768];

// ------------------------------ helpers -------------------------------------
__device__ __forceinline__ u32 smem_u32(const void* p) {
    u32 a;
    asm("{ .reg .u64 t; cvta.to.shared.u64 t, %1; cvt.u32.u64 %0, t; }"
        : "=r"(a) : "l"(p));
    return a;
}

// Tile image: rows x 128 cols fp16, row stride 256B, 16B chunks
// XOR-swizzled by (row & 7) for conflict-free ldmatrix.
__device__ __forceinline__ u32 tile_off(int r, int k) {
    return (u32)r * 256 + ((u32)(((k >> 3) ^ (r & 7))) << 4) + ((u32)(k & 7) << 1);
}

__device__ __forceinline__ void ldsm_x4(u32 addr, u32& r0, u32& r1, u32& r2, u32& r3) {
    asm volatile("ldmatrix.sync.aligned.m8n8.x4.shared.b16 {%0,%1,%2,%3}, [%4];"
                 : "=r"(r0), "=r"(r1), "=r"(r2), "=r"(r3) : "r"(addr));
}

__device__ __forceinline__ void mma_f16(float* c, const u32* a, const u32* b) {
    asm volatile(
        "mma.sync.aligned.m16n8k16.row.col.f32.f16.f16.f32 "
        "{%0,%1,%2,%3}, {%4,%5,%6,%7}, {%8,%9}, {%0,%1,%2,%3};"
        : "+f"(c[0]), "+f"(c[1]), "+f"(c[2]), "+f"(c[3])
        : "r"(a[0]), "r"(a[1]), "r"(a[2]), "r"(a[3]), "r"(b[0]), "r"(b[1]));
}

__device__ __forceinline__ void cpasync16(u32 dst, const void* src) {
    asm volatile("cp.async.cg.shared.global [%0], [%1], 16;"
                 :: "r"(dst), "l"(src));
}

__device__ __forceinline__ void cpasync16z(u32 dst, const void* src, int srcsz) {
    asm volatile("cp.async.cg.shared.global [%0], [%1], 16, %2;"
                 :: "r"(dst), "l"(src), "r"(srcsz));
}

__device__ __forceinline__ void red_h2(__half* p, float a, float b) {
    __half2 h = __floats2half2_rn(a, b);
    asm volatile("red.global.add.noftz.f16x2 [%0], %1;"
                 :: "l"(p), "r"(*(u32*)&h) : "memory");
}

__device__ __forceinline__ float sigmoidf(float x) {
    return 1.0f / (1.0f + __expf(-x));
}

__device__ __forceinline__ float4 h4_to_f4(uint2 v) {
    float2 a = __half22float2(*(__half2*)&v.x);
    float2 b = __half22float2(*(__half2*)&v.y);
    return make_float4(a.x, a.y, b.x, b.y);
}

// gemm_mma smem: A tile (16KB, swizzled, 64 rows) | W (32KB)
#define SA_H 0
#define SW0  16384
#define GEMM_SMEM 49152
// fused kernel smem: EP/A region (17408B: A swizzled 16KB OR 64x272B tile)
// | W (32KB) at 17408 (128B aligned)
#define EPS   272
#define FW0   17408
#define FUSED_SMEM (17408 + 32768)

// --------------------------- weight prep kernel -----------------------------
__global__ void wprep_kernel(const float* __restrict__ w1,
                             const float* __restrict__ w2,
                             char* __restrict__ dst)
{
    int mat = blockIdx.x;                       // 0..9
    const float* W = (mat < 5) ? (w1 + mat * 16384) : (w2 + (mat - 5) * 16384);
    char* base = dst + (long long)mat * 32768;
    for (int i = threadIdx.x; i < 16384; i += blockDim.x) {
        int n = i >> 7, k = i & 127;
        float v = W[k * 128 + n];
        *(__half*)(base + tile_off(n, k)) = __float2half_rn(v);
    }
}

// ------------------------------ HMMA GEMM (4-mat) ---------------------------
// For j in [0, nmat): C[:, j*128 : +128] = A[M,128] @ W[nibble_j(wmap)] + bias
// CTA tile 64(M) x 128(N), 256 threads, warp tile 32x32, 3 CTAs/SM.
extern "C" __global__ __launch_bounds__(256, 3) void gemm_mma(
    const void* __restrict__ Ain, int aHalf, const char* __restrict__ Wp,
    const float* __restrict__ b1, const float* __restrict__ b2,
    __half* __restrict__ C, long long M, int ldc, int wmap, int nmat)
{
    extern __shared__ char smem[];
    const u32 sb = smem_u32(smem);
    const int tid = threadIdx.x, lane = tid & 31, wid = tid >> 5;
    const int wm = wid & 1;
    const int wn = wid >> 1;
    const long long row0 = (long long)blockIdx.x * 64;

    {
        int mat = wmap & 0xF;
        const char* ws = Wp + (long long)mat * 32768;
        #pragma unroll 4
        for (int i = tid; i < 2048; i += 256)
            cpasync16(sb + SW0 + i * 16, ws + (long long)i * 16);
    }
    if (aHalf) {
        const char* Ab = (const char*)Ain;
        #pragma unroll 2
        for (int i = tid; i < 1024; i += 256) {
            int r = i >> 4, ch = i & 15;
            long long row = row0 + r;
            u32 dst = sb + SA_H + (u32)r * 256 + ((u32)(ch ^ (r & 7)) << 4);
            cpasync16z(dst, Ab + row * 256 + ch * 16, (row < M) ? 16 : 0);
        }
    }
    asm volatile("cp.async.commit_group;");

    if (!aHalf) {
        const float4* A4 = (const float4*)Ain;
        #pragma unroll 4
        for (int i = tid; i < 2048; i += 256) {
            int r = i >> 5, c4 = i & 31;
            long long row = row0 + r;
            float4 v = (row < M) ? A4[row * 32 + c4]
                                 : make_float4(0.f, 0.f, 0.f, 0.f);
            __half2 h01 = __floats2half2_rn(v.x, v.y);
            __half2 h23 = __floats2half2_rn(v.z, v.w);
            *(uint2*)(smem + SA_H + tile_off(r, c4 * 4)) =
                make_uint2(*(u32*)&h01, *(u32*)&h23);
        }
    }

    const int rA = wm * 32 + (lane & 15);
    const int haA = lane >> 4;
    const int rBoff = (lane & 7) + ((lane >> 4) << 3);
    const int hbB = (lane >> 3) & 1;

    u32 aBase[2]; int aSel[2];
    #pragma unroll
    for (int mf = 0; mf < 2; mf++) {
        int r = rA + mf * 16;
        aBase[mf] = sb + SA_H + (u32)r * 256;
        aSel[mf] = r & 7;
    }
    u32 bBase[2]; int bSel[2];
    #pragma unroll
    for (int np = 0; np < 2; np++) {
        int r = wn * 32 + np * 16 + rBoff;
        bBase[np] = sb + SW0 + (u32)r * 256;
        bSel[np] = r & 7;
    }

    const int mloc = wm * 32 + (lane >> 2);

    #pragma unroll 1
    for (int j = 0; j < nmat; j++) {
        const int mat = (wmap >> (4 * j)) & 0xF;
        const float* bias = (mat < 5) ? (b1 + mat * 128) : (b2 + (mat - 5) * 128);

        asm volatile("cp.async.wait_group 0;");
        __syncthreads();

        float acc[2][4][4];
        #pragma unroll
        for (int mf = 0; mf < 2; mf++)
            #pragma unroll
            for (int nf = 0; nf < 4; nf++)
                #pragma unroll
                for (int q = 0; q < 4; q++) acc[mf][nf][q] = 0.f;

        #pragma unroll 1
        for (int kb = 0; kb < 8; kb++) {
            const int c2 = kb * 2;
            u32 ah[2][4], bh[4][2];
            #pragma unroll
            for (int mf = 0; mf < 2; mf++) {
                u32 x = (u32)((c2 + haA) ^ aSel[mf]) << 4;
                ldsm_x4(aBase[mf] + x, ah[mf][0], ah[mf][1], ah[mf][2], ah[mf][3]);
            }
            #pragma unroll
            for (int np = 0; np < 2; np++) {
                u32 x = (u32)((c2 + hbB) ^ bSel[np]) << 4;
                ldsm_x4(bBase[np] + x, bh[2*np][0], bh[2*np][1],
                                       bh[2*np+1][0], bh[2*np+1][1]);
            }
            #pragma unroll
            for (int mf = 0; mf < 2; mf++)
                #pragma unroll
                for (int nf = 0; nf < 4; nf++)
                    mma_f16(acc[mf][nf], ah[mf], bh[nf]);
        }

        __syncthreads();
        if (j + 1 < nmat) {
            int mat2 = (wmap >> (4 * (j + 1))) & 0xF;
            const char* ws = Wp + (long long)mat2 * 32768;
            #pragma unroll 4
            for (int i = tid; i < 2048; i += 256)
                cpasync16(sb + SW0 + i * 16, ws + (long long)i * 16);
            asm volatile("cp.async.commit_group;");
        }

        __half* Cj = C + j * 128;
        #pragma unroll
        for (int mf = 0; mf < 2; mf++) {
            long long rowa = row0 + mloc + mf * 16;
            long long rowb = rowa + 8;
            #pragma unroll
            for (int nf = 0; nf < 4; nf++) {
                int n = wn * 32 + nf * 8 + (lane & 3) * 2;
                float bx = __ldg(bias + n), by = __ldg(bias + n + 1);
                if (rowa < M) {
                    __half2 o = __floats2half2_rn(acc[mf][nf][0] + bx,
                                                  acc[mf][nf][1] + by);
                    *(__half2*)(Cj + rowa * (long long)ldc + n) = o;
                }
                if (rowb < M) {
                    __half2 o = __floats2half2_rn(acc[mf][nf][2] + bx,
                                                  acc[mf][nf][3] + by);
                    *(__half2*)(Cj + rowb * (long long)ldc + n) = o;
                }
            }
        }
    }
}

// --------------------- fused Ce-GEMM + edge kernel --------------------------
// Phase 1: tile Ce[64,128] = A[64,128] @ W + bias  (A fp32; W pre-swizzled)
// Phase 2: tile staged in smem; per-edge: e_new = Ce + Dh[src] + Eh[dst];
//          sigma = sigmoid; num/den fp16x2 reductions; eout = relu(e_new).
template <bool OUT_HALF>
__global__ __launch_bounds__(256, 3) void gemm_edge(
    const float* __restrict__ Ain, const char* __restrict__ Wmat,
    const float* __restrict__ bias, const __half* __restrict__ NB,
    const int* __restrict__ src, const int* __restrict__ dst,
    __half* __restrict__ num, __half* __restrict__ den,
    void* __restrict__ eout, long long E)
{
    extern __shared__ char smem[];
    const u32 sb = smem_u32(smem);
    const int tid = threadIdx.x, lane = tid & 31, wid = tid >> 5;
    const int wm = wid & 1;
    const int wn = wid >> 1;
    const long long row0 = (long long)blockIdx.x * 64;

    // W via cp.async
    #pragma unroll 4
    for (int i = tid; i < 2048; i += 256)
        cpasync16(sb + FW0 + i * 16, Wmat + (long long)i * 16);
    asm volatile("cp.async.commit_group;");

    // A fp32 -> fp16, swizzled into EP region (stride 256 during GEMM)
    {
        const float4* A4 = (const float4*)Ain;
        #pragma unroll 4
        for (int i = tid; i < 2048; i += 256) {
            int r = i >> 5, c4 = i & 31;
            long long row = row0 + r;
            float4 v = (row < E) ? A4[row * 32 + c4]
                                 : make_float4(0.f, 0.f, 0.f, 0.f);
            __half2 h01 = __floats2half2_rn(v.x, v.y);
            __half2 h23 = __floats2half2_rn(v.z, v.w);
            *(uint2*)(smem + tile_off(r, c4 * 4)) =
                make_uint2(*(u32*)&h01, *(u32*)&h23);
        }
    }

    const int rA = wm * 32 + (lane & 15);
    const int haA = lane >> 4;
    const int rBoff = (lane & 7) + ((lane >> 4) << 3);
    const int hbB = (lane >> 3) & 1;

    u32 aBase[2]; int aSel[2];
    #pragma unroll
    for (int mf = 0; mf < 2; mf++) {
        int r = rA + mf * 16;
        aBase[mf] = sb + (u32)r * 256;
        aSel[mf] = r & 7;
    }
    u32 bBase[2]; int bSel[2];
    #pragma unroll
    for (int np = 0; np < 2; np++) {
        int r = wn * 32 + np * 16 + rBoff;
        bBase[np] = sb + FW0 + (u32)r * 256;
        bSel[np] = r & 7;
    }

    asm volatile("cp.async.wait_group 0;");
    __syncthreads();

    float acc[2][4][4];
    #pragma unroll
    for (int mf = 0; mf < 2; mf++)
        #pragma unroll
        for (int nf = 0; nf < 4; nf++)
            #pragma unroll
            for (int q = 0; q < 4; q++) acc[mf][nf][q] = 0.f;

    #pragma unroll 1
    for (int kb = 0; kb < 8; kb++) {
        const int c2 = kb * 2;
        u32 ah[2][4], bh[4][2];
        #pragma unroll
        for (int mf = 0; mf < 2; mf++) {
            u32 x = (u32)((c2 + haA) ^ aSel[mf]) << 4;
            ldsm_x4(aBase[mf] + x, ah[mf][0], ah[mf][1], ah[mf][2], ah[mf][3]);
        }
        #pragma unroll
        for (int np = 0; np < 2; np++) {
            u32 x = (u32)((c2 + hbB) ^ bSel[np]) << 4;
            ldsm_x4(bBase[np] + x, bh[2*np][0], bh[2*np][1],
                                   bh[2*np+1][0], bh[2*np+1][1]);
        }
        #pragma unroll
        for (int mf = 0; mf < 2; mf++)
            #pragma unroll
            for (int nf = 0; nf < 4; nf++)
                mma_f16(acc[mf][nf], ah[mf], bh[nf]);
    }

    __syncthreads();   // all warps done reading A region

    // Stage Ce tile in smem: 64 rows x 128 halfs, row stride EPS=272B
    // (conflict-free STS: word bank = 4*row + (lane&3) + const -> 32 distinct)
    const int mloc = wm * 32 + (lane >> 2);
    #pragma unroll
    for (int mf = 0; mf < 2; mf++) {
        int ra = mloc + mf * 16;
        #pragma unroll
        for (int nf = 0; nf < 4; nf++) {
            int n = wn * 32 + nf * 8 + (lane & 3) * 2;
            float bx = __ldg(bias + n), by = __ldg(bias + n + 1);
            __half2 oa = __floats2half2_rn(acc[mf][nf][0] + bx,
                                           acc[mf][nf][1] + by);
            __half2 ob = __floats2half2_rn(acc[mf][nf][2] + bx,
                                           acc[mf][nf][3] + by);
            *(__half2*)(smem + ra * EPS + n * 2) = oa;
            *(__half2*)(smem + (ra + 8) * EPS + n * 2) = ob;
        }
    }
    __syncthreads();

    // Phase 2: 8 warps x 8 edges each; lane owns cols lane*4..+3
    #pragma unroll 1
    for (int it = 0; it < 8; it++) {
        const int lrow = wid * 8 + it;
        const long long e = row0 + lrow;
        if (e >= E) break;
        const int s = __ldg(src + e);
        const int d = __ldg(dst + e);

        const float4 ce = h4_to_f4(*(const uint2*)(smem + lrow * EPS + lane * 8));
        const __half* nbs = NB + (long long)s * 512;
        const __half* nbd = NB + (long long)d * 512;
        const float4 dh = h4_to_f4(*(const uint2*)(nbs + 256 + lane * 4));
        const float4 eh = h4_to_f4(*(const uint2*)(nbd + 384 + lane * 4));
        const float4 bh = h4_to_f4(*(const uint2*)(nbs + 128 + lane * 4));

        float4 en;
        en.x = ce.x + dh.x + eh.x;
        en.y = ce.y + dh.y + eh.y;
        en.z = ce.z + dh.z + eh.z;
        en.w = ce.w + dh.w + eh.w;

        float4 sg;
        sg.x = sigmoidf(en.x); sg.y = sigmoidf(en.y);
        sg.z = sigmoidf(en.z); sg.w = sigmoidf(en.w);

        __half* np = num + (long long)d * 128 + lane * 4;
        __half* dp = den + (long long)d * 128 + lane * 4;
        red_h2(np,     sg.x * bh.x, sg.y * bh.y);
        red_h2(np + 2, sg.z * bh.z, sg.w * bh.w);
        red_h2(dp,     sg.x, sg.y);
        red_h2(dp + 2, sg.z, sg.w);

        const long long eo = e * 128 + lane * 4;
        if (OUT_HALF) {
            __half2 r01 = __floats2half2_rn(fmaxf(en.x, 0.f), fmaxf(en.y, 0.f));
            __half2 r23 = __floats2half2_rn(fmaxf(en.z, 0.f), fmaxf(en.w, 0.f));
            *(uint2*)((__half*)eout + eo) = make_uint2(*(u32*)&r01, *(u32*)&r23);
        } else {
            float4 ro;
            ro.x = fmaxf(en.x, 0.f); ro.y = fmaxf(en.y, 0.f);
            ro.z = fmaxf(en.z, 0.f); ro.w = fmaxf(en.w, 0.f);
            *(float4*)((float*)eout + eo) = ro;
        }
    }
}

// ------------------------------ finalize ------------------------------------
__global__ __launch_bounds__(256) void finalize_kernel(
    const __half* __restrict__ Abuf, long long lda,
    const __half* __restrict__ num, const __half* __restrict__ den,
    float* __restrict__ outp, long long N)
{
    long long i = (long long)blockIdx.x * 256 + threadIdx.x;   // group-of-4 idx
    if (i >= N * 32) return;
    long long row = i >> 5;
    int c = (int)(i & 31);
    float4 a = h4_to_f4(*(const uint2*)(Abuf + row * lda + c * 4));
    float4 n = h4_to_f4(*(const uint2*)(num + i * 4));
    float4 dd = h4_to_f4(*(const uint2*)(den + i * 4));
    float4 o;
    o.x = fmaxf(a.x + n.x / (dd.x + 1e-6f), 0.f);
    o.y = fmaxf(a.y + n.y / (dd.y + 1e-6f), 0.f);
    o.z = fmaxf(a.z + n.z / (dd.z + 1e-6f), 0.f);
    o.w = fmaxf(a.w + n.w / (dd.w + 1e-6f), 0.f);
    ((float4*)outp)[i] = o;
}

// ------------------------------ launch --------------------------------------
extern "C" void kernel_launch(void* const* d_in, const int* in_sizes, int n_in,
                              void* d_out, int out_size)
{
    const float* node  = (const float*)d_in[0];
    const float* edge  = (const float*)d_in[1];
    const float* angle = (const float*)d_in[2];
    const int*   gei   = (const int*)d_in[3];
    const int*   lei   = (const int*)d_in[4];
    const float* w1    = (const float*)d_in[5];
    const float* b1    = (const float*)d_in[6];
    const float* w2    = (const float*)d_in[7];
    const float* b2    = (const float*)d_in[8];

    float* out   = (float*)d_out;
    float* h_out = out;
    float* e_out = out + N_NODES * D;
    float* a_out = out + N_NODES * D + N_EDGES * D;

    __half *NB1, *NB2, *e1, *num1, *den1, *num2, *den2;
    char* Wsp;
    cudaGetSymbolAddress((void**)&NB1,  g_NB1);
    cudaGetSymbolAddress((void**)&NB2,  g_NB2);
    cudaGetSymbolAddress((void**)&e1,   g_e1);
    cudaGetSymbolAddress((void**)&num1, g_num1);
    cudaGetSymbolAddress((void**)&den1, g_den1);
    cudaGetSymbolAddress((void**)&num2, g_num2);
    cudaGetSymbolAddress((void**)&den2, g_den2);
    cudaGetSymbolAddress((void**)&Wsp,  g_Wsplit);

    cudaFuncSetAttribute(gemm_mma,
                         cudaFuncAttributeMaxDynamicSharedMemorySize, GEMM_SMEM);
    cudaFuncSetAttribute(gemm_edge<true>,
                         cudaFuncAttributeMaxDynamicSharedMemorySize, FUSED_SMEM);
    cudaFuncSetAttribute(gemm_edge<false>,
                         cudaFuncAttributeMaxDynamicSharedMemorySize, FUSED_SMEM);

    // Side stream + events for fork/join inside graph capture.
    cudaStream_t s1;
    cudaStreamCreateWithFlags(&s1, cudaStreamNonBlocking);
    cudaEvent_t ev_fork, ev_ms, ev_e1, ev_f1;
    cudaEventCreateWithFlags(&ev_fork, cudaEventDisableTiming);
    cudaEventCreateWithFlags(&ev_ms,   cudaEventDisableTiming);
    cudaEventCreateWithFlags(&ev_e1,   cudaEventDisableTiming);
    cudaEventCreateWithFlags(&ev_f1,   cudaEventDisableTiming);

    cudaEventRecord(ev_fork, 0);
    cudaStreamWaitEvent(s1, ev_fork, 0);

    // s1: zero segment-sum accumulators (overlaps wprep/G1 on s0)
    cudaMemsetAsync(num1, 0, N_NODES * D * sizeof(__half), s1);
    cudaMemsetAsync(den1, 0, N_NODES * D * sizeof(__half), s1);
    cudaMemsetAsync(num2, 0, N_EDGES * D * sizeof(__half), s1);
    cudaMemsetAsync(den2, 0, N_EDGES * D * sizeof(__half), s1);
    cudaEventRecord(ev_ms, s1);

    // s0: weight prep, node GEMM (4 mats)
    wprep_kernel<<<10, 256>>>(w1, w2, Wsp);
    gemm_mma<<<1563, 256, GEMM_SMEM>>>(node, 0, Wsp, b1, b2, NB1,
                                       N_NODES, 512, 0x4310, 4);

    // s0: fused Ce-GEMM + edge1 (needs NB1 + memsets); writes e1/num1/den1
    cudaStreamWaitEvent(0, ev_ms, 0);
    gemm_edge<true><<<9375, 256, FUSED_SMEM>>>(
        edge, Wsp + 2LL * 32768, b1 + 2 * 128, NB1,
        gei, gei + N_EDGES, num1, den1, e1, N_EDGES);
    cudaEventRecord(ev_e1, 0);

    // s1: finalize1 (needs fused1) — overlaps e1->NB2 GEMM on s0
    cudaStreamWaitEvent(s1, ev_e1, 0);
    finalize_kernel<<<12500, 256, 0, s1>>>(NB1, 512, num1, den1,
                                           h_out, N_NODES);
    cudaEventRecord(ev_f1, s1);

    // s0: layer-2 big GEMM, fused Ca-GEMM + edge2, finalize2
    gemm_mma<<<9375, 256, GEMM_SMEM>>>(e1, 1, Wsp, b1, b2, NB2,
                                       N_EDGES, 512, 0x9865, 4);
    gemm_edge<false><<<9375, 256, FUSED_SMEM>>>(
        angle, Wsp + 7LL * 32768, b2 + 2 * 128, NB2,
        lei, lei + N_ANGLES, num2, den2, a_out, N_ANGLES);
    finalize_kernel<<<75000, 256>>>(NB2, 512, num2, den2, e_out, N_EDGES);

    // Join s1 back into s0 before returning.
    cudaStreamWaitEvent(0, ev_f1, 0);

    cudaEventDestroy(ev_fork);
    cudaEventDestroy(ev_ms);
    cudaEventDestroy(ev_e1);
    cudaEventDestroy(ev_f1);
    cudaStreamDestroy(s1);
}